// round 1
// baseline (speedup 1.0000x reference)
#include <cuda_runtime.h>
#include <math.h>

// Problem constants
#define N_NODES 20000
#define N_EDGES 320000
#define C 50
#define CP 64            // padded channel stride
#define NB 10
#define NGR 20
#define NL 3
#define KH 100           // hidden width of radial MLP
#define WCOLS 300        // 6*C output cols of radial MLP
#define WROW 320         // padded row stride of w buffer
#define FSTRIDE (9*CP)   // 576 floats per node feature row

// ---------------- device scratch (static globals; no allocation) ----------------
__device__ int   g_cnt;
__device__ int   g_src[N_EDGES];
__device__ int   g_dst[N_EDGES];
__device__ float g_Y[N_EDGES * 8];          // Y1 (3) + Y2 (5)
__device__ float2 g_bv[N_EDGES];            // basis values (<=2 active)
__device__ int   g_bi[N_EDGES];             // packed basis indices k0 | k1<<16
__device__ float g_hidden[KH * N_EDGES];    // [k][e] K-major for coalesced GEMM A loads
__device__ float g_w[(size_t)N_EDGES * WROW];
__device__ float g_f0[N_NODES * FSTRIDE];
__device__ float g_f1[N_NODES * FSTRIDE];
__device__ float g_agg[N_NODES * FSTRIDE];

// ---------------- helpers ----------------
__device__ __forceinline__ float sigmf(float x) { return 1.0f / (1.0f + __expf(-x)); }
__device__ __forceinline__ float siluf(float x) { return x / (1.0f + __expf(-x)); }

typedef unsigned long long u64;
__device__ __forceinline__ u64 pack2(float lo, float hi) {
    u64 r; asm("mov.b64 %0, {%1,%2};" : "=l"(r) : "f"(lo), "f"(hi)); return r;
}
__device__ __forceinline__ void unpack2(u64 v, float& lo, float& hi) {
    asm("mov.b64 {%0,%1}, %2;" : "=f"(lo), "=f"(hi) : "l"(v));
}
__device__ __forceinline__ u64 ffma2(u64 a, u64 b, u64 c) {
    u64 d; asm("fma.rn.f32x2 %0, %1, %2, %3;" : "=l"(d) : "l"(a), "l"(b), "l"(c)); return d;
}

// ---------------- kernels ----------------

// zero f0 + output + edge counter
__global__ void k_zero(float* __restrict__ out) {
    int i = blockIdx.x * blockDim.x + threadIdx.x;
    if (i == 0) g_cnt = 0;
    if (i < NGR * 4) out[i] = 0.0f;
    const int tot = N_NODES * FSTRIDE / 4;
    float4 z = make_float4(0.f, 0.f, 0.f, 0.f);
    for (int j = i; j < tot; j += gridDim.x * blockDim.x) ((float4*)g_f0)[j] = z;
}

__global__ void k_zero_agg() {
    int i = blockIdx.x * blockDim.x + threadIdx.x;
    const int tot = N_NODES * FSTRIDE / 4;
    float4 z = make_float4(0.f, 0.f, 0.f, 0.f);
    for (int j = i; j < tot; j += gridDim.x * blockDim.x) ((float4*)g_agg)[j] = z;
}

// Per-edge geometry: spherical harmonics + sparse radial basis; compact active edges.
__global__ void k_edges(const float* __restrict__ pos,
                        const int* __restrict__ esrc, const int* __restrict__ edst) {
    int e = blockIdx.x * blockDim.x + threadIdx.x;
    if (e >= N_EDGES) return;
    int s = esrc[e], d = edst[e];
    float vx = pos[3*s+0] - pos[3*d+0];
    float vy = pos[3*s+1] - pos[3*d+1];
    float vz = pos[3*s+2] - pos[3*d+2];
    float r = sqrtf(vx*vx + vy*vy + vz*vz);
    // centers at j*2/11 (j=1..10), step=2/11: d_j = r*5.5 - j, window |d_j|<1
    float t = r * 5.5f;
    float b0 = 0.f, b1 = 0.f; int k0 = 0, k1 = 0, na = 0;
    int j0 = (int)floorf(t);
    #pragma unroll
    for (int jj = 0; jj < 2; jj++) {
        int j = j0 + jj;
        if (j >= 1 && j <= 10) {
            float dd = t - (float)j;
            if (dd > -1.f && dd < 1.f) {
                float b = cospif(0.5f * dd) * 3.1622776601683795f; // * sqrt(NB)
                if (na == 0) { k0 = j - 1; b0 = b; } else { k1 = j - 1; b1 = b; }
                na++;
            }
        }
    }
    if (na == 0) return;   // zero basis -> silu(0)=0 -> w=0 -> message=0 exactly
    float rs  = (r > 1e-9f) ? r : 1.0f;
    float inv = 1.0f / rs;
    float ux = vx * inv, uy = vy * inv, uz = vz * inv;
    int p = atomicAdd(&g_cnt, 1);
    g_src[p] = s; g_dst[p] = d;
    g_bv[p]  = make_float2(b0, b1);
    g_bi[p]  = k0 | (k1 << 16);
    float* Y = g_Y + p * 8;
    const float s3 = 1.7320508075688772f, s15 = 3.872983346207417f, s5 = 2.2360679774997896f;
    Y[0] = s3 * ux; Y[1] = s3 * uy; Y[2] = s3 * uz;
    Y[3] = s15 * ux * uy;
    Y[4] = s15 * uy * uz;
    Y[5] = 0.5f * s5 * (3.f * uz * uz - 1.f);
    Y[6] = s15 * ux * uz;
    Y[7] = 0.5f * s15 * (ux * ux - uy * uy);
}

// f0[n][0][c] = x @ Wembed
__global__ void k_embed(const float* __restrict__ x, const float* __restrict__ We) {
    int n = blockIdx.x, c = threadIdx.x;
    if (c >= C) return;
    float acc = 0.f;
    #pragma unroll
    for (int j = 0; j < 10; j++) acc += x[n*10 + j] * We[j*C + c];
    g_f0[n * FSTRIDE + c] = acc;
}

// hidden[k][e] = silu(b0*Wr1[k0][k] + b1*Wr1[k1][k])   (2-term sparse basis)
__global__ void k_hidden(const float* __restrict__ Wr1l) {
    int e = blockIdx.x * blockDim.x + threadIdx.x;
    if (e >= g_cnt) return;
    int bi = g_bi[e]; float2 bv = g_bv[e];
    const float* r0 = Wr1l + (bi & 0xffff) * KH;
    const float* r1 = Wr1l + (bi >> 16) * KH;
    #pragma unroll 4
    for (int k = 0; k < KH; k++) {
        float h = bv.x * r0[k] + bv.y * r1[k];
        g_hidden[k * N_EDGES + e] = siluf(h);
    }
}

// w[e][0..299] = hidden[e] @ Wr2   — fp32x2-packed SGEMM, 128x64 tile, BK=16
__global__ void __launch_bounds__(256) k_gemm(const float* __restrict__ Bmat) {
    __shared__ float As[16][128];
    __shared__ float Bs[16][64];
    int cnt = g_cnt;
    int etile = blockIdx.x * 128;
    if (etile >= cnt) return;
    int ntile = blockIdx.y * 64;
    int tid = threadIdx.x;
    int tc = tid & 7, tr = tid >> 3;
    u64 acc[4][4];
    #pragma unroll
    for (int i = 0; i < 4; i++)
        #pragma unroll
        for (int j = 0; j < 4; j++) acc[i][j] = 0ull;

    for (int kb = 0; kb < KH; kb += 16) {
        #pragma unroll
        for (int rep = 0; rep < 2; rep++) {
            int i4 = tid + rep * 256;
            int kk = i4 >> 5, m = (i4 & 31) * 4;
            int gk = kb + kk;
            float4 v = make_float4(0.f,0.f,0.f,0.f);
            if (gk < KH) v = *(const float4*)(g_hidden + (size_t)gk * N_EDGES + etile + m);
            *(float4*)(&As[kk][m]) = v;
        }
        {
            int kk = tid >> 4, nn = (tid & 15) * 4;
            int gk = kb + kk, col = ntile + nn;
            float4 v = make_float4(0.f,0.f,0.f,0.f);
            if (gk < KH && col < WCOLS) v = *(const float4*)(Bmat + gk * WCOLS + col);
            *(float4*)(&Bs[kk][nn]) = v;
        }
        __syncthreads();
        #pragma unroll
        for (int kk = 0; kk < 16; kk++) {
            float4 av = *(const float4*)(&As[kk][tr * 4]);
            u64 a0 = pack2(av.x, av.x), a1 = pack2(av.y, av.y);
            u64 a2 = pack2(av.z, av.z), a3 = pack2(av.w, av.w);
            ulonglong2 bb0 = *(const ulonglong2*)(&Bs[kk][tc * 8]);
            ulonglong2 bb1 = *(const ulonglong2*)(&Bs[kk][tc * 8 + 4]);
            acc[0][0]=ffma2(a0,bb0.x,acc[0][0]); acc[0][1]=ffma2(a0,bb0.y,acc[0][1]);
            acc[0][2]=ffma2(a0,bb1.x,acc[0][2]); acc[0][3]=ffma2(a0,bb1.y,acc[0][3]);
            acc[1][0]=ffma2(a1,bb0.x,acc[1][0]); acc[1][1]=ffma2(a1,bb0.y,acc[1][1]);
            acc[1][2]=ffma2(a1,bb1.x,acc[1][2]); acc[1][3]=ffma2(a1,bb1.y,acc[1][3]);
            acc[2][0]=ffma2(a2,bb0.x,acc[2][0]); acc[2][1]=ffma2(a2,bb0.y,acc[2][1]);
            acc[2][2]=ffma2(a2,bb1.x,acc[2][2]); acc[2][3]=ffma2(a2,bb1.y,acc[2][3]);
            acc[3][0]=ffma2(a3,bb0.x,acc[3][0]); acc[3][1]=ffma2(a3,bb0.y,acc[3][1]);
            acc[3][2]=ffma2(a3,bb1.x,acc[3][2]); acc[3][3]=ffma2(a3,bb1.y,acc[3][3]);
        }
        __syncthreads();
    }
    #pragma unroll
    for (int i = 0; i < 4; i++) {
        int row = etile + tr * 4 + i;
        if (row >= cnt) continue;
        float* wr = g_w + (size_t)row * WROW + ntile + tc * 8;
        #pragma unroll
        for (int j = 0; j < 4; j++) {
            float lo, hi; unpack2(acc[i][j], lo, hi);
            int col = ntile + tc * 8 + 2 * j;
            if (col     < WCOLS) wr[2*j]     = lo;
            if (col + 1 < WCOLS) wr[2*j + 1] = hi;
        }
    }
}

// messages + segment-sum into g_agg (atomics). 64 lanes per edge (c<50 active).
__global__ void __launch_bounds__(256) k_msg(int cur) {
    int e    = blockIdx.x * 4 + (threadIdx.x >> 6);
    int lane = threadIdx.x & 63;
    if (e >= g_cnt || lane >= C) return;
    const float* __restrict__ f = cur ? g_f1 : g_f0;
    int src = g_src[e], dst = g_dst[e];
    const float* w  = g_w + (size_t)e * WROW;
    const float* fs = f + src * FSTRIDE;
    float* agg = g_agg + dst * FSTRIDE;
    float w0 = w[lane],       w1 = w[C + lane],   w2 = w[2*C + lane];
    float w3 = w[3*C + lane], w4 = w[4*C + lane], w5 = w[5*C + lane];
    float s = fs[lane];
    const float* Y = g_Y + e * 8;
    atomicAdd(agg + lane, (w0 + w3) * s);
    float a1 = w1 * s;
    #pragma unroll
    for (int t = 0; t < 3; t++)
        atomicAdd(agg + (1+t)*CP + lane, a1 * Y[t] + w4 * fs[(1+t)*CP + lane]);
    float a2 = w2 * s;
    #pragma unroll
    for (int t = 0; t < 5; t++)
        atomicAdd(agg + (4+t)*CP + lane, a2 * Y[3+t] + w5 * fs[(4+t)*CP + lane]);
}

// self-interaction + gate + nonlinearity. 4 nodes x 64 lanes per iter, 8 iters/block.
__global__ void __launch_bounds__(256) k_node(int cur,
        const float* __restrict__ Wsl, const float* __restrict__ Wgl) {
    __shared__ float Ws[3 * C * C];     // 30KB
    __shared__ float fsh[4][9 * C];     // 7.2KB
    __shared__ float h0sh[4][C];
    const float* __restrict__ f  = cur ? g_f1 : g_f0;
    float* __restrict__ fn       = cur ? g_f0 : g_f1;
    int tid = threadIdx.x;
    for (int i = tid; i < 3 * C * C; i += 256) Ws[i] = Wsl[i];
    int grp = tid >> 6, d = tid & 63;
    int base = blockIdx.x * 32;
    for (int it = 0; it < 8; it++) {
        int nb = base + it * 4;
        __syncthreads();
        for (int i = tid; i < 4 * 9 * C; i += 256) {
            int nn = i / (9 * C); int rem = i - nn * (9 * C);
            int m = rem / C; int c = rem - m * C;
            fsh[nn][rem] = f[(nb + nn) * FSTRIDE + m * CP + c];
        }
        __syncthreads();
        int n = nb + grp;
        float h[9];
        if (d < C) {
            const float* ag = g_agg + n * FSTRIDE;
            #pragma unroll
            for (int m = 0; m < 9; m++) h[m] = 0.25f * ag[m * CP + d]; // /sqrt(16)
            const float* fr = fsh[grp];
            for (int c = 0; c < C; c++) {
                float w0 = Ws[c * C + d];
                float w1 = Ws[C*C + c * C + d];
                float w2 = Ws[2*C*C + c * C + d];
                h[0] += fr[c] * w0;
                h[1] += fr[C + c]   * w1; h[2] += fr[2*C + c] * w1; h[3] += fr[3*C + c] * w1;
                h[4] += fr[4*C + c] * w2; h[5] += fr[5*C + c] * w2; h[6] += fr[6*C + c] * w2;
                h[7] += fr[7*C + c] * w2; h[8] += fr[8*C + c] * w2;
            }
            h0sh[grp][d] = h[0];
        }
        __syncthreads();
        if (d < C) {
            float gj0 = 0.f, gj1 = 0.f;
            const float* hp = h0sh[grp];
            for (int c = 0; c < C; c++) {
                float hv = hp[c];
                gj0 += hv * Wgl[c * 2 * C + d];
                gj1 += hv * Wgl[c * 2 * C + C + d];
            }
            float g0 = sigmf(gj0), g1 = sigmf(gj1);
            float* fo = fn + n * FSTRIDE;
            fo[d] = h[0] * sigmf(h[0]);       // silu
            #pragma unroll
            for (int m = 1; m < 4; m++) fo[m * CP + d] = h[m] * g0;
            #pragma unroll
            for (int m = 4; m < 9; m++) fo[m * CP + d] = h[m] * g1;
        }
    }
}

// readout: per-graph sum of f0 @ Wout, two-stage (shared then global atomics)
__global__ void __launch_bounds__(256) k_out(int cur, const float* __restrict__ Wout,
        const int* __restrict__ batch, float* __restrict__ out) {
    __shared__ float acc[NGR * 4];
    int tid = threadIdx.x;
    if (tid < NGR * 4) acc[tid] = 0.f;
    __syncthreads();
    int n = blockIdx.x * 256 + tid;
    if (n < N_NODES) {
        const float* f = (cur ? g_f1 : g_f0) + n * FSTRIDE;
        float o0 = 0.f, o1 = 0.f, o2 = 0.f, o3 = 0.f;
        for (int c = 0; c < C; c++) {
            float v = f[c];
            o0 += v * Wout[c*4+0]; o1 += v * Wout[c*4+1];
            o2 += v * Wout[c*4+2]; o3 += v * Wout[c*4+3];
        }
        int b = batch[n] * 4;
        atomicAdd(&acc[b+0], o0); atomicAdd(&acc[b+1], o1);
        atomicAdd(&acc[b+2], o2); atomicAdd(&acc[b+3], o3);
    }
    __syncthreads();
    if (tid < NGR * 4) atomicAdd(&out[tid], acc[tid] * 0.031622776601683794f); // /sqrt(1000)
}

// ---------------- launch ----------------
extern "C" void kernel_launch(void* const* d_in, const int* in_sizes, int n_in,
                              void* d_out, int out_size) {
    const float* pos   = (const float*)d_in[0];
    const float* x     = (const float*)d_in[1];
    const float* We    = (const float*)d_in[2];
    const float* Wr1   = (const float*)d_in[3];
    const float* Wr2   = (const float*)d_in[4];
    const float* Wself = (const float*)d_in[5];
    const float* Wgate = (const float*)d_in[6];
    const float* Wout  = (const float*)d_in[7];
    const int*   esrc  = (const int*)d_in[8];
    const int*   edst  = (const int*)d_in[9];
    const int*   batch = (const int*)d_in[10];
    float* out = (float*)d_out;

    k_zero<<<1024, 256>>>(out);
    k_edges<<<(N_EDGES + 255) / 256, 256>>>(pos, esrc, edst);
    k_embed<<<N_NODES, 64>>>(x, We);

    int cur = 0;
    for (int l = 0; l < NL; l++) {
        k_hidden<<<(N_EDGES + 255) / 256, 256>>>(Wr1 + l * NB * KH);
        k_gemm<<<dim3(N_EDGES / 128, 5), 256>>>(Wr2 + l * KH * WCOLS);
        k_zero_agg<<<1024, 256>>>();
        k_msg<<<(N_EDGES + 3) / 4, 256>>>(cur);
        k_node<<<625, 256>>>(cur, Wself + l * 3 * C * C, Wgate + l * C * 2 * C);
        cur ^= 1;
    }
    k_out<<<79, 256>>>(cur, Wout, batch, out);
}

// round 2
// speedup vs baseline: 2.8576x; 2.8576x over previous
#include <cuda_runtime.h>
#include <math.h>

// Problem constants
#define N_NODES 20000
#define N_EDGES 320000
#define C 50
#define NB 10
#define NGR 20
#define NL 3
#define FSTRIDE 456          // 9*C = 450 used + pad to 8-float alignment
#define TB 11264             // table bins over t = 5.5*r in [0,11]; width 1/1024
#define TROW 256             // table row stride (250 used)

// ---------------- device scratch (static globals; no allocation) ----------------
__device__ int   g_hist[N_NODES];
__device__ int   g_off[N_NODES + 1];
__device__ int   g_cur[N_NODES];
__device__ int   g_src[N_EDGES];
__device__ float g_t[N_EDGES];            // t*1024 (table coordinate)
__device__ float g_Y[N_EDGES * 8];        // Y1(3) + Y2(5)
__device__ float g_tab[(TB + 1) * TROW];  // per-layer w(r) table, rebuilt each layer
__device__ float g_f0[N_NODES * FSTRIDE];
__device__ float g_f1[N_NODES * FSTRIDE];
__device__ float g_agg[N_NODES * FSTRIDE];

__device__ __forceinline__ float sigmf(float x) { return 1.0f / (1.0f + __expf(-x)); }
__device__ __forceinline__ float siluf(float x) { return x / (1.0f + __expf(-x)); }

// ---------------- kernels ----------------

// zero f0 + output + histogram
__global__ void k_zero(float* __restrict__ out) {
    int i = blockIdx.x * blockDim.x + threadIdx.x;
    if (i < NGR * 4) out[i] = 0.0f;
    if (i < N_NODES) g_hist[i] = 0;
    const int tot = N_NODES * FSTRIDE / 4;
    float4 z = make_float4(0.f, 0.f, 0.f, 0.f);
    for (int j = i; j < tot; j += gridDim.x * blockDim.x) ((float4*)g_f0)[j] = z;
}

// pass1: histogram of active edges per dst
__global__ void k_edges1(const float* __restrict__ pos,
                         const int* __restrict__ esrc, const int* __restrict__ edst) {
    int e = blockIdx.x * blockDim.x + threadIdx.x;
    if (e >= N_EDGES) return;
    int s = esrc[e], d = edst[e];
    float vx = pos[3*s+0] - pos[3*d+0];
    float vy = pos[3*s+1] - pos[3*d+1];
    float vz = pos[3*s+2] - pos[3*d+2];
    float t = sqrtf(vx*vx + vy*vy + vz*vz) * 5.5f;
    if (t > 0.0f && t < 11.0f) atomicAdd(&g_hist[d], 1);
}

// exclusive prefix scan of 20000 bins, single block of 1024
__global__ void k_scan() {
    __shared__ int sums[1024];
    int tid = threadIdx.x;
    int base = tid * 20;
    int loc[20];
    int s = 0;
    #pragma unroll
    for (int i = 0; i < 20; i++) {
        int idx = base + i;
        int v = (idx < N_NODES) ? g_hist[idx] : 0;
        loc[i] = s; s += v;
    }
    sums[tid] = s;
    __syncthreads();
    for (int off = 1; off < 1024; off <<= 1) {
        int v = 0;
        if (tid >= off) v = sums[tid - off];
        __syncthreads();
        if (tid >= off) sums[tid] += v;
        __syncthreads();
    }
    int excl = sums[tid] - s;
    #pragma unroll
    for (int i = 0; i < 20; i++) {
        int idx = base + i;
        if (idx < N_NODES) { g_off[idx] = excl + loc[i]; g_cur[idx] = excl + loc[i]; }
    }
    if (tid == 1023) g_off[N_NODES] = sums[1023];
}

// pass2: recompute geometry, place active edges sorted by dst
__global__ void k_edges2(const float* __restrict__ pos,
                         const int* __restrict__ esrc, const int* __restrict__ edst) {
    int e = blockIdx.x * blockDim.x + threadIdx.x;
    if (e >= N_EDGES) return;
    int s = esrc[e], d = edst[e];
    float vx = pos[3*s+0] - pos[3*d+0];
    float vy = pos[3*s+1] - pos[3*d+1];
    float vz = pos[3*s+2] - pos[3*d+2];
    float r = sqrtf(vx*vx + vy*vy + vz*vz);
    float t = r * 5.5f;
    if (!(t > 0.0f && t < 11.0f)) return;
    int p = atomicAdd(&g_cur[d], 1);
    g_src[p] = s;
    g_t[p]   = t * 1024.0f;   // table coordinate, < 11264
    float inv = 1.0f / r;     // r>0 guaranteed here
    float ux = vx * inv, uy = vy * inv, uz = vz * inv;
    const float s3 = 1.7320508075688772f, s15 = 3.872983346207417f, s5 = 2.2360679774997896f;
    float* Y = g_Y + p * 8;
    Y[0] = s3 * ux; Y[1] = s3 * uy; Y[2] = s3 * uz;
    Y[3] = s15 * ux * uy;
    Y[4] = s15 * uy * uz;
    Y[5] = 0.5f * s5 * (3.f * uz * uz - 1.f);
    Y[6] = s15 * ux * uz;
    Y[7] = 0.5f * s15 * (ux * ux - uy * uy);
}

// f0[n][0][c] = x @ Wembed   (4 nodes x 64 lanes per block)
__global__ void __launch_bounds__(256) k_embed(const float* __restrict__ x,
                                               const float* __restrict__ We) {
    int n = blockIdx.x * 4 + (threadIdx.x >> 6);
    int c = threadIdx.x & 63;
    if (n >= N_NODES || c >= C) return;
    float acc = 0.f;
    #pragma unroll
    for (int j = 0; j < 10; j++) acc += x[n*10 + j] * We[j*C + c];
    g_f0[n * FSTRIDE + c] = acc;
}

// Build w(t) table for this layer: rows = bins of t, 250 cols
// col layout: [0..49]=w0+w3, [50..99]=w1, [100..149]=w2, [150..199]=w4, [200..249]=w5
__global__ void __launch_bounds__(256) k_wtab(const float* __restrict__ Wr1l,
                                              const float* __restrict__ Wr2l) {
    __shared__ float hid[8][100];
    int row0 = blockIdx.x * 8;
    int tid = threadIdx.x;
    // stage A: hidden = silu(basis @ Wr1) for 8 rows
    for (int idx = tid; idx < 800; idx += 256) {
        int rr = idx / 100, h = idx - 100 * rr;
        float t = (float)(row0 + rr) * (1.0f / 1024.0f);
        float pre = 0.f;
        #pragma unroll
        for (int k = 1; k <= 10; k++) {
            float d = t - (float)k;
            if (d > -1.f && d < 1.f)
                pre += cospif(0.5f * d) * 3.1622776601683795f * Wr1l[(k-1)*100 + h];
        }
        hid[rr][h] = siluf(pre);
    }
    __syncthreads();
    // stage B: w columns
    if (tid < 250) {
        int comp = tid / 50, c = tid - 50 * comp;
        int colA = (comp == 0) ? c : (comp == 1) ? 50 + c : (comp == 2) ? 100 + c
                  : (comp == 3) ? 200 + c : 250 + c;
        float acc[8];
        #pragma unroll
        for (int rr = 0; rr < 8; rr++) acc[rr] = 0.f;
        for (int k = 0; k < 100; k++) {
            float w = Wr2l[k * 300 + colA];
            if (comp == 0) w += Wr2l[k * 300 + 150 + c];
            #pragma unroll
            for (int rr = 0; rr < 8; rr++) acc[rr] += hid[rr][k] * w;
        }
        #pragma unroll
        for (int rr = 0; rr < 8; rr++) {
            int row = row0 + rr;
            if (row <= TB) g_tab[row * TROW + tid] = acc[rr];
        }
    }
}

// messages, dst-sorted: one 64-lane group per dst node, register accumulation, plain stores
__global__ void __launch_bounds__(256) k_msg(int cur) {
    int g = threadIdx.x >> 6, c = threadIdx.x & 63;
    int n = blockIdx.x * 4 + g;
    if (n >= N_NODES) return;
    const float* __restrict__ f = cur ? g_f1 : g_f0;
    int e0 = g_off[n], e1 = g_off[n + 1];
    bool act = (c < C);
    float a0=0,a1=0,a2=0,a3=0,a4=0,a5=0,a6=0,a7=0,a8=0;
    for (int e = e0; e < e1; e++) {
        int src = g_src[e];
        float tt = g_t[e];
        int i0 = (int)tt;
        float fr = tt - (float)i0;
        const float* T0 = g_tab + i0 * TROW;
        const float* T1 = T0 + TROW;
        const float* fs = f + src * FSTRIDE;
        const float* Y  = g_Y + e * 8;
        if (act) {
            float W0 = T0[c]       + fr * (T1[c]       - T0[c]);
            float W1 = T0[50 + c]  + fr * (T1[50 + c]  - T0[50 + c]);
            float W2 = T0[100 + c] + fr * (T1[100 + c] - T0[100 + c]);
            float W4 = T0[150 + c] + fr * (T1[150 + c] - T0[150 + c]);
            float W5 = T0[200 + c] + fr * (T1[200 + c] - T0[200 + c]);
            float s = fs[c];
            a0 += W0 * s;
            float b1 = W1 * s;
            a1 += b1 * Y[0] + W4 * fs[C + c];
            a2 += b1 * Y[1] + W4 * fs[2*C + c];
            a3 += b1 * Y[2] + W4 * fs[3*C + c];
            float b2 = W2 * s;
            a4 += b2 * Y[3] + W5 * fs[4*C + c];
            a5 += b2 * Y[4] + W5 * fs[5*C + c];
            a6 += b2 * Y[5] + W5 * fs[6*C + c];
            a7 += b2 * Y[6] + W5 * fs[7*C + c];
            a8 += b2 * Y[7] + W5 * fs[8*C + c];
        }
    }
    if (act) {
        float* ag = g_agg + n * FSTRIDE;
        const float sc = 0.25f;   // 1/sqrt(16)
        ag[c]       = a0 * sc;
        ag[C + c]   = a1 * sc;  ag[2*C + c] = a2 * sc;  ag[3*C + c] = a3 * sc;
        ag[4*C + c] = a4 * sc;  ag[5*C + c] = a5 * sc;  ag[6*C + c] = a6 * sc;
        ag[7*C + c] = a7 * sc;  ag[8*C + c] = a8 * sc;
    }
}

// self-interaction + gate + nonlinearity: 1 warp per node (lane handles d and d+32), 8 nodes/block
__global__ void __launch_bounds__(256) k_node(int cur,
        const float* __restrict__ Wsl, const float* __restrict__ Wgl) {
    __shared__ float Ws[3 * C * C];        // 30KB
    __shared__ float fsh[8][9 * C];        // 14.4KB
    __shared__ float h0sh[8][C];
    const float* __restrict__ f  = cur ? g_f1 : g_f0;
    float* __restrict__ fn       = cur ? g_f0 : g_f1;
    int tid = threadIdx.x;
    for (int i = tid; i < 3 * C * C; i += 256) Ws[i] = Wsl[i];
    int nb = blockIdx.x * 8;
    for (int i = tid; i < 8 * 9 * C; i += 256) {
        int nn = i / (9 * C); int rem = i - nn * (9 * C);
        fsh[nn][rem] = f[(nb + nn) * FSTRIDE + rem];
    }
    __syncthreads();
    int w = tid >> 5, lane = tid & 31;
    int n = nb + w;
    int d = lane, d2 = lane + 32;
    bool hasd2 = (d2 < C);
    float h[9], h2[9];
    const float* ag = g_agg + n * FSTRIDE;
    #pragma unroll
    for (int m = 0; m < 9; m++) {
        h[m]  = ag[m * C + d];
        h2[m] = hasd2 ? ag[m * C + d2] : 0.f;
    }
    const float* fr = fsh[w];
    for (int c = 0; c < C; c++) {
        float w0 = Ws[c * C + d];
        float w1 = Ws[C*C + c * C + d];
        float w2 = Ws[2*C*C + c * C + d];
        float v;
        v = fr[c];       h[0] += v * w0;
        float v1 = fr[C + c], v2 = fr[2*C + c], v3 = fr[3*C + c];
        h[1] += v1 * w1; h[2] += v2 * w1; h[3] += v3 * w1;
        float v4 = fr[4*C + c], v5 = fr[5*C + c], v6 = fr[6*C + c];
        float v7 = fr[7*C + c], v8 = fr[8*C + c];
        h[4] += v4 * w2; h[5] += v5 * w2; h[6] += v6 * w2;
        h[7] += v7 * w2; h[8] += v8 * w2;
        if (hasd2) {
            float u0 = Ws[c * C + d2];
            float u1 = Ws[C*C + c * C + d2];
            float u2 = Ws[2*C*C + c * C + d2];
            h2[0] += fr[c] * u0;
            h2[1] += v1 * u1; h2[2] += v2 * u1; h2[3] += v3 * u1;
            h2[4] += v4 * u2; h2[5] += v5 * u2; h2[6] += v6 * u2;
            h2[7] += v7 * u2; h2[8] += v8 * u2;
        }
    }
    h0sh[w][d] = h[0];
    if (hasd2) h0sh[w][d2] = h2[0];
    __syncwarp();
    // gate
    float gj0 = 0.f, gj1 = 0.f, gk0 = 0.f, gk1 = 0.f;
    const float* hp = h0sh[w];
    for (int c = 0; c < C; c++) {
        float hv = hp[c];
        gj0 += hv * Wgl[c * 2 * C + d];
        gj1 += hv * Wgl[c * 2 * C + C + d];
        if (hasd2) {
            gk0 += hv * Wgl[c * 2 * C + d2];
            gk1 += hv * Wgl[c * 2 * C + C + d2];
        }
    }
    float* fo = fn + n * FSTRIDE;
    {
        float g0 = sigmf(gj0), g1 = sigmf(gj1);
        fo[d] = h[0] * sigmf(h[0]);
        #pragma unroll
        for (int m = 1; m < 4; m++) fo[m * C + d] = h[m] * g0;
        #pragma unroll
        for (int m = 4; m < 9; m++) fo[m * C + d] = h[m] * g1;
    }
    if (hasd2) {
        float g0 = sigmf(gk0), g1 = sigmf(gk1);
        fo[d2] = h2[0] * sigmf(h2[0]);
        #pragma unroll
        for (int m = 1; m < 4; m++) fo[m * C + d2] = h2[m] * g0;
        #pragma unroll
        for (int m = 4; m < 9; m++) fo[m * C + d2] = h2[m] * g1;
    }
}

// readout: per-graph sum of f[:, :, 0] @ Wout
__global__ void __launch_bounds__(256) k_out(int cur, const float* __restrict__ Wout,
        const int* __restrict__ batch, float* __restrict__ out) {
    __shared__ float acc[NGR * 4];
    int tid = threadIdx.x;
    if (tid < NGR * 4) acc[tid] = 0.f;
    __syncthreads();
    int n = blockIdx.x * 256 + tid;
    if (n < N_NODES) {
        const float* f = (cur ? g_f1 : g_f0) + n * FSTRIDE;
        float o0 = 0.f, o1 = 0.f, o2 = 0.f, o3 = 0.f;
        for (int c = 0; c < C; c++) {
            float v = f[c];
            o0 += v * Wout[c*4+0]; o1 += v * Wout[c*4+1];
            o2 += v * Wout[c*4+2]; o3 += v * Wout[c*4+3];
        }
        int b = batch[n] * 4;
        atomicAdd(&acc[b+0], o0); atomicAdd(&acc[b+1], o1);
        atomicAdd(&acc[b+2], o2); atomicAdd(&acc[b+3], o3);
    }
    __syncthreads();
    if (tid < NGR * 4) atomicAdd(&out[tid], acc[tid] * 0.031622776601683794f); // /sqrt(1000)
}

// ---------------- launch ----------------
extern "C" void kernel_launch(void* const* d_in, const int* in_sizes, int n_in,
                              void* d_out, int out_size) {
    const float* pos   = (const float*)d_in[0];
    const float* x     = (const float*)d_in[1];
    const float* We    = (const float*)d_in[2];
    const float* Wr1   = (const float*)d_in[3];
    const float* Wr2   = (const float*)d_in[4];
    const float* Wself = (const float*)d_in[5];
    const float* Wgate = (const float*)d_in[6];
    const float* Wout  = (const float*)d_in[7];
    const int*   esrc  = (const int*)d_in[8];
    const int*   edst  = (const int*)d_in[9];
    const int*   batch = (const int*)d_in[10];
    float* out = (float*)d_out;

    k_zero<<<1024, 256>>>(out);
    k_edges1<<<(N_EDGES + 255) / 256, 256>>>(pos, esrc, edst);
    k_scan<<<1, 1024>>>();
    k_edges2<<<(N_EDGES + 255) / 256, 256>>>(pos, esrc, edst);
    k_embed<<<N_NODES / 4, 256>>>(x, We);

    int cur = 0;
    for (int l = 0; l < NL; l++) {
        k_wtab<<<(TB + 1 + 7) / 8, 256>>>(Wr1 + l * NB * 100, Wr2 + l * 100 * 300);
        k_msg<<<N_NODES / 4, 256>>>(cur);
        k_node<<<N_NODES / 8, 256>>>(cur, Wself + l * 3 * C * C, Wgate + l * C * 2 * C);
        cur ^= 1;
    }
    k_out<<<79, 256>>>(cur, Wout, batch, out);
}